// round 4
// baseline (speedup 1.0000x reference)
#include <cuda_runtime.h>
#include <math.h>

#define NB   16
#define CIN  64
#define CE   64
#define HIN  256
#define HOUT 128

// ---------------- device-global scratch ----------------
__device__ float g_pooled[NB * CIN];
__device__ int   g_sel_idx[NB * 2];
__device__ float g_sel_w[NB * 2];

// packed fp32x2 helpers (Blackwell packed-FP32 pipe; only reachable via PTX)
__device__ __forceinline__ unsigned long long ffma2(unsigned long long a,
                                                    unsigned long long b,
                                                    unsigned long long c) {
    unsigned long long d;
    asm("fma.rn.f32x2 %0, %1, %2, %3;" : "=l"(d) : "l"(a), "l"(b), "l"(c));
    return d;
}
__device__ __forceinline__ unsigned long long pack2(float lo, float hi) {
    unsigned long long d;
    asm("mov.b64 %0, {%1, %2};" : "=l"(d) : "f"(lo), "f"(hi));
    return d;
}
__device__ __forceinline__ void unpack2(unsigned long long v, float& lo, float& hi) {
    asm("mov.b64 {%0, %1}, %2;" : "=f"(lo), "=f"(hi) : "l"(v));
}

// ---------------- kernel 1: global average pool per (b, c) ----------------
__global__ void pool_kernel(const float* __restrict__ x) {
    int bc = blockIdx.x;
    const float4* p = (const float4*)(x + (size_t)bc * (HIN * HIN));
    float s = 0.f;
    for (int i = threadIdx.x; i < (HIN * HIN) / 4; i += 256) {
        float4 v = p[i];
        s += (v.x + v.y) + (v.z + v.w);
    }
    __shared__ float red[8];
    for (int o = 16; o; o >>= 1) s += __shfl_xor_sync(0xffffffffu, s, o);
    if ((threadIdx.x & 31) == 0) red[threadIdx.x >> 5] = s;
    __syncthreads();
    if (threadIdx.x < 8) {
        s = red[threadIdx.x];
        for (int o = 4; o; o >>= 1) s += __shfl_xor_sync(0xffu, s, o);
        if (threadIdx.x == 0) g_pooled[bc] = s * (1.f / (HIN * HIN));
    }
}

// ---------------- kernel 2: gate ----------------
__global__ void gate_kernel(const float* __restrict__ gw, const float* __restrict__ gb) {
    int b = threadIdx.x;
    if (b >= NB) return;
    float logits[4];
    for (int e = 0; e < 4; e++) {
        float s = gb[e];
        for (int c = 0; c < CIN; c++) s += g_pooled[b * CIN + c] * gw[e * CIN + c];
        logits[e] = s;
    }
    float mx = logits[0];
    for (int e = 1; e < 4; e++) mx = fmaxf(mx, logits[e]);
    float g[4], sum = 0.f;
    for (int e = 0; e < 4; e++) { g[e] = expf(logits[e] - mx); sum += g[e]; }
    for (int e = 0; e < 4; e++) g[e] /= sum;
    int i0 = 0;
    for (int e = 1; e < 4; e++) if (g[e] > g[i0]) i0 = e;
    int i1 = -1;
    for (int e = 0; e < 4; e++) {
        if (e == i0) continue;
        if (i1 < 0 || g[e] > g[i1]) i1 = e;
    }
    float den = g[i0] + g[i1] + 1e-8f;
    g_sel_idx[b * 2 + 0] = i0; g_sel_w[b * 2 + 0] = g[i0] / den;
    g_sel_idx[b * 2 + 1] = i1; g_sel_w[b * 2 + 1] = g[i1] / den;
}

// ---------------- kernel 3: fused conv + bias + BN + GELU + slot weight ----
// Block tile: 32x32 output px, 256 threads; each thread: 4 pixels (rows
// oy+8p) x 8 output channels (co-group of 8 in gridDim.z) = 32 fp32 accs
// held as 16 packed f32x2. Input patch staged in smem PARITY-SPLIT (even/odd
// columns in separate planes) so stride-2 xv reads are conflict-free.
template <int K, int D, int E>
__global__ __launch_bounds__(256)
void conv_kernel(const float* __restrict__ x, const float* __restrict__ w,
                 const float* __restrict__ cb,
                 const float* __restrict__ bn_scale, const float* __restrict__ bn_bias,
                 const float* __restrict__ bn_mean,  const float* __restrict__ bn_var,
                 float* __restrict__ out) {
    constexpr int PAD   = D * (K - 1) / 2;
    constexpr int PDIM  = 63 + (K - 1) * D;       // patch height == width
    constexpr int PWH   = (PDIM + 1) / 2;         // half-width (parity plane)
    constexpr int PLANE = PDIM * PWH;

    const int z   = blockIdx.z;
    const int cog = z & 7;
    const int s   = (z >> 3) & 1;
    const int b   = z >> 4;

    if (g_sel_idx[b * 2 + s] != E) return;  // uniform per block

    __shared__ float patch[2 * PLANE];                   // [parity][row][halfcol]
    __shared__ __align__(16) float wsm[K * K * 8];       // [tap][co within group]

    const int tid = threadIdx.x;
    const int tx  = tid & 31;
    const int ty  = tid >> 5;
    const int ox  = blockIdx.x * 32 + tx;
    const int oyb = blockIdx.y * 32 + ty;                // pixel rows oyb + 8p
    const int iy0 = blockIdx.y * 64 - PAD;
    const int ix0 = blockIdx.x * 64 - PAD;

    unsigned long long acc[4][4];
#pragma unroll
    for (int p = 0; p < 4; p++)
#pragma unroll
        for (int j = 0; j < 4; j++) acc[p][j] = 0ull;

    for (int cin = 0; cin < CIN; cin++) {
        __syncthreads();
        // stage input patch, parity-split, zero-padded
        const float* xb = x + ((size_t)(b * CIN + cin)) * (HIN * HIN);
        for (int i = tid; i < PDIM * PDIM; i += 256) {
            int r = i / PDIM, q = i - r * PDIM;          // constexpr divisor
            int gy = iy0 + r, gx = ix0 + q;
            float v = 0.f;
            if ((unsigned)gy < (unsigned)HIN && (unsigned)gx < (unsigned)HIN)
                v = __ldg(xb + gy * HIN + gx);
            patch[(q & 1) * PLANE + r * PWH + (q >> 1)] = v;
        }
        // stage weights for this cin: wsm[tap*8 + c]
        const float* wb = w + cin * (K * K);
        for (int i = tid; i < K * K * 8; i += 256) {
            int t = i >> 3, c = i & 7;
            wsm[i] = __ldg(wb + (size_t)(cog * 8 + c) * (CIN * K * K) + t);
        }
        __syncthreads();

        // per-pixel row base offsets (plane-relative)
        int rb[4];
#pragma unroll
        for (int p = 0; p < 4; p++) rb[p] = ((ty + 8 * p) * 2) * PWH + tx;

#pragma unroll 1
        for (int kh = 0; kh < K; kh++) {
            const int rowoff = kh * D * PWH;
            const unsigned long long* wq =
                (const unsigned long long*)(wsm + kh * K * 8);
#pragma unroll
            for (int kw = 0; kw < K; kw++) {
                const int par  = (kw * D) & 1;
                const int half = (kw * D) >> 1;
                const float* pp = patch + par * PLANE + rowoff + half;
                unsigned long long w0 = wq[kw * 4 + 0];
                unsigned long long w1 = wq[kw * 4 + 1];
                unsigned long long w2 = wq[kw * 4 + 2];
                unsigned long long w3 = wq[kw * 4 + 3];
#pragma unroll
                for (int p = 0; p < 4; p++) {
                    float xv = pp[rb[p]];
                    unsigned long long xx = pack2(xv, xv);
                    acc[p][0] = ffma2(xx, w0, acc[p][0]);
                    acc[p][1] = ffma2(xx, w1, acc[p][1]);
                    acc[p][2] = ffma2(xx, w2, acc[p][2]);
                    acc[p][3] = ffma2(xx, w3, acc[p][3]);
                }
            }
        }
    }

    // epilogue: bias + BN + exact GELU + slot weight
    const float sw = g_sel_w[b * 2 + s];
#pragma unroll
    for (int j = 0; j < 4; j++) {
#pragma unroll
        for (int h = 0; h < 2; h++) {
            int   c    = j * 2 + h;
            int   co   = cog * 8 + c;
            float inv  = bn_scale[E * CE + co] * rsqrtf(bn_var[E * CE + co] + 1e-5f);
            float beta = bn_bias[E * CE + co] - bn_mean[E * CE + co] * inv;
            float bc   = cb[co];
            size_t base = ((size_t)(b * 128 + s * 64 + co)) * (HOUT * HOUT) + ox;
#pragma unroll
            for (int p = 0; p < 4; p++) {
                float lo, hi;
                unpack2(acc[p][j], lo, hi);
                float a  = h ? hi : lo;
                float y  = (a + bc) * inv + beta;
                float gv = 0.5f * y * (1.f + erff(y * 0.70710678118654752f));
                out[base + (size_t)(oyb + 8 * p) * HOUT] = gv * sw;
            }
        }
    }
}

// ---------------- launch ----------------
extern "C" void kernel_launch(void* const* d_in, const int* in_sizes, int n_in,
                              void* d_out, int out_size) {
    const float* x   = (const float*)d_in[0];
    const float* w0  = (const float*)d_in[1];
    const float* b0  = (const float*)d_in[2];
    const float* w1  = (const float*)d_in[3];
    const float* b1  = (const float*)d_in[4];
    const float* w2  = (const float*)d_in[5];
    const float* b2  = (const float*)d_in[6];
    const float* w3  = (const float*)d_in[7];
    const float* b3  = (const float*)d_in[8];
    const float* bns = (const float*)d_in[9];
    const float* bnb = (const float*)d_in[10];
    const float* bnm = (const float*)d_in[11];
    const float* bnv = (const float*)d_in[12];
    const float* gw  = (const float*)d_in[13];
    const float* gb  = (const float*)d_in[14];
    float* out = (float*)d_out;

    pool_kernel<<<NB * CIN, 256>>>(x);
    gate_kernel<<<1, 32>>>(gw, gb);

    // grid: 4x4 tiles of 32x32 px, z = b(slowest) * slot * 8 co-groups
    dim3 grid(HOUT / 32, HOUT / 32, NB * 2 * 8);
    conv_kernel<3, 1, 0><<<grid, 256>>>(x, w0, b0, bns, bnb, bnm, bnv, out);
    conv_kernel<5, 2, 1><<<grid, 256>>>(x, w1, b1, bns, bnb, bnm, bnv, out);
    conv_kernel<7, 3, 2><<<grid, 256>>>(x, w2, b2, bns, bnb, bnm, bnv, out);
    conv_kernel<9, 4, 3><<<grid, 256>>>(x, w3, b3, bns, bnb, bnm, bnv, out);
}